// round 7
// baseline (speedup 1.0000x reference)
#include <cuda_runtime.h>
#include <cuda_bf16.h>
#include <math.h>
#include <stdint.h>

// ----------------------------------------------------------------------------
// k' = k(0.8+0.28g) + 0.52 g v ; v' = 0.8 v + 0.2 u_t ; g = g(k^2+u^2).
// Out: tanh(k_final).   (64-pt GL quadrature folded into host-built table.)
//
// 1) Contraction: only the LAST W=512 steps from (0,0) matter (validated).
//    If n < W, zero-padding the front is exact ((0,0) fixed under u=0).
// 2) Host-built linearized table g ~ a_i + b_i*s (2048 entries over [0,24]),
//    passed by value as 16KB kernel param. Zero GPU prologue.
// 3) Picard + affine scan on ONE WARP: 32 threads x 16 steps, all state in
//    registers, 5-level shuffle scan, zero __syncthreads. 12 sweeps.
// ----------------------------------------------------------------------------

#define GLN 64
#define NTAB 2048
#define S_MAX 24.0f
#define INV_DS ((float)NTAB / S_MAX)
#define W 512
#define TPB 32
#define CHUNK 16          // W / TPB
#define NSWEEP 12

struct TabParam { float2 e[NTAB]; };   // 16384 bytes, by value

// warp-inclusive scan of affine composites: F∘G -> A=A_F*A_G, B=fma(A_F,B_G,B_F)
__device__ __forceinline__ void warp_scan_affine(float& A, float& B, int lane) {
    #pragma unroll
    for (int off = 1; off < 32; off <<= 1) {
        float Ag = __shfl_up_sync(0xFFFFFFFFu, A, off);
        float Bg = __shfl_up_sync(0xFFFFFFFFu, B, off);
        if (lane >= off) { B = fmaf(A, Bg, B); A *= Ag; }
    }
}

__global__ void __launch_bounds__(TPB, 1)
run_kernel(TabParam tp, const float* __restrict__ u,
           float* __restrict__ out, int n) {
    __shared__ float2 tab[NTAB];   // 16 KB
    const int lane = threadIdx.x;

    // table: kernel-param (const bank) -> SMEM, vectorized
    {
        const float4* src = (const float4*)tp.e;
        float4* dst = (float4*)tab;
        #pragma unroll
        for (int j = 0; j < NTAB / 2 / TPB; ++j)       // 32 float4 per thread
            dst[lane + j * TPB] = src[lane + j * TPB];
    }

    // u window (zero-padded front if n < W)
    float su2[CHUNK], uu[CHUNK];
    const int base = n - W + lane * CHUNK;
    #pragma unroll
    for (int j = 0; j < CHUNK; ++j) {
        int gi = base + j;
        float x = (gi >= 0) ? u[gi] : 0.0f;
        uu[j] = x;
        su2[j] = x * x;
    }

    // ---- v scan: v_t = 0.8 v_{t-1} + 0.2 u_t, v_0 = 0 ----------------------
    float vprev[CHUNK];
    {
        float Al[CHUNK], Bl[CHUNK];
        float A = 1.0f, B = 0.0f;
        #pragma unroll
        for (int j = 0; j < CHUNK; ++j) {
            B = fmaf(0.8f, B, 0.2f * uu[j]);
            A = 0.8f * A;
            Al[j] = A; Bl[j] = B;
        }
        float As = A, Bs = B;
        warp_scan_affine(As, Bs, lane);
        float vstart = __shfl_up_sync(0xFFFFFFFFu, Bs, 1);  // exclusive (v0=0)
        if (lane == 0) vstart = 0.0f;
        vprev[0] = vstart;
        #pragma unroll
        for (int j = 1; j < CHUNK; ++j)
            vprev[j] = fmaf(Al[j - 1], vstart, Bl[j - 1]);
    }

    __syncwarp();   // table writes visible to all lanes

    // ---- Picard sweeps ------------------------------------------------------
    float k[CHUNK];
    #pragma unroll
    for (int j = 0; j < CHUNK; ++j) k[j] = 0.0f;
    float klast = 0.0f;   // this thread's k[CHUNK-1] from previous sweep

    #pragma unroll 1
    for (int sw = 0; sw < NSWEEP; ++sw) {
        float knb = __shfl_up_sync(0xFFFFFFFFu, klast, 1);
        if (lane == 0) knb = 0.0f;

        // per-element g from PREVIOUS trajectory (independent lookups)
        float at[CHUNK], bt[CHUNK];
        #pragma unroll
        for (int j = 0; j < CHUNK; ++j) {
            float kp = (j == 0) ? knb : k[j - 1];
            float s  = fmaf(kp, kp, su2[j]);
            int idx  = (int)fmaf(s, INV_DS, 0.5f);        // round to nearest
            idx = (idx < NTAB - 1) ? idx : (NTAB - 1);
            float2 ab = tab[idx];
            float g = fmaf(ab.y, s, ab.x);
            at[j] = fmaf(0.28f, g, 0.8f);
            bt[j] = 0.52f * g * vprev[j];
        }

        // local inclusive composite prefixes
        float Al[CHUNK], Bl[CHUNK];
        float A = 1.0f, B = 0.0f;
        #pragma unroll
        for (int j = 0; j < CHUNK; ++j) {
            B = fmaf(at[j], B, bt[j]);
            A = at[j] * A;
            Al[j] = A; Bl[j] = B;
        }

        // warp scan + exclusive start (k_0 = 0 -> kstart = B_excl)
        float As = A, Bs = B;
        warp_scan_affine(As, Bs, lane);
        float kstart = __shfl_up_sync(0xFFFFFFFFu, Bs, 1);
        if (lane == 0) kstart = 0.0f;

        // rebuild trajectory
        #pragma unroll
        for (int j = 0; j < CHUNK; ++j)
            k[j] = fmaf(Al[j], kstart, Bl[j]);
        klast = k[CHUNK - 1];
    }

    if (lane == TPB - 1) *out = tanhf(k[CHUNK - 1]);
}

// ---------------------------------------------------------------------------
// Host: Gauss-Legendre n=64 + table build (double precision, input-indep).
// ---------------------------------------------------------------------------
static void host_leggauss64(double* x, double* w) {
    const int n = GLN;
    const double PI = 3.14159265358979323846;
    for (int i = 0; i < n; ++i) {
        double xi = cos(PI * (i + 0.75) / (n + 0.5));
        double p0 = 1.0, p1 = 0.0, pp = 1.0;
        for (int it = 0; it < 100; ++it) {
            p0 = 1.0; p1 = 0.0;
            for (int j = 1; j <= n; ++j) {
                double p2 = p1; p1 = p0;
                p0 = ((2.0 * j - 1.0) * xi * p1 - (j - 1.0) * p2) / j;
            }
            pp = n * (xi * p0 - p1) / (xi * xi - 1.0);
            double dx = p0 / pp;
            xi -= dx;
            if (fabs(dx) < 1e-15) break;
        }
        p0 = 1.0; p1 = 0.0;
        for (int j = 1; j <= n; ++j) {
            double p2 = p1; p1 = p0;
            p0 = ((2.0 * j - 1.0) * xi * p1 - (j - 1.0) * p2) / j;
        }
        pp = n * (xi * p0 - p1) / (xi * xi - 1.0);
        x[i] = xi;
        w[i] = 2.0 / ((1.0 - xi * xi) * pp * pp);
    }
}

static double host_g(double s, const double* X, const double* EW) {
    double d = sqrt(s);
    double acc = 0.0;
    for (int q = 0; q < GLN; ++q) {
        double th = tanh(d * X[q]);
        acc += EW[q] * (1.0 - th * th);
    }
    return acc * 0.15915494309189535;   // 1/(2*pi)
}

static void host_build_table(TabParam* tp) {
    double x[GLN], wq[GLN], X[GLN], EW[GLN];
    host_leggauss64(x, wq);
    for (int q = 0; q < GLN; ++q) {
        X[q]  = x[q] * 5.0;
        EW[q] = wq[q] * 5.0 * exp(-X[q] * X[q] * 0.5);
    }
    const double ds = (double)S_MAX / (double)NTAB;
    for (int i = 0; i < NTAB; ++i) {
        double s  = i * ds;
        double h  = 0.5 * ds;
        double sl = (s - h > 0.0) ? (s - h) : 0.0;
        double sh = s + h;
        double g0 = host_g(s,  X, EW);
        double gm = host_g(sl, X, EW);
        double gp = host_g(sh, X, EW);
        double bb = (gp - gm) / (sh - sl);
        tp->e[i].x = (float)(g0 - bb * s);
        tp->e[i].y = (float)bb;
    }
}

// ---------------------------------------------------------------------------
extern "C" void kernel_launch(void* const* d_in, const int* in_sizes, int n_in,
                              void* d_out, int out_size) {
    (void)n_in; (void)out_size;
    const float* u = (const float*)d_in[0];
    float* out = (float*)d_out;
    int n = in_sizes[0];

    static TabParam tp;
    host_build_table(&tp);   // deterministic, host-side, input-independent

    run_kernel<<<1, TPB>>>(tp, u, out, n);
}

// round 8
// speedup vs baseline: 1.2289x; 1.2289x over previous
#include <cuda_runtime.h>
#include <cuda_bf16.h>
#include <math.h>
#include <stdint.h>

// ----------------------------------------------------------------------------
// k' = k(0.8+0.28g) + 0.52 g v ; v' = 0.8 v + 0.2 u_t ; g = g(k^2+u^2).
// Out: tanh(k_final).   (64-pt GL quadrature folded into host-built table.)
//
// 1) Contraction: only LAST W=512 steps from (0,0) matter (validated R3/R4).
// 2) Host-built linearized table g ~ a_i + b_i*s (2048 entries over [0,24]),
//    passed by value as 16KB kernel param. Zero GPU prologue.
// 3) Picard + affine scan on ONE WARP (32 thr x 16 steps), register-lean:
//    persistent state = su2[16], cj[16], k[16] only; at/bt fused into the
//    prefix compose so sweeps keep just Al/Bl live. 8 sweeps (R7 showed full
//    convergence at <=12; per-sweep contraction ~0.15). Magic-constant
//    float->smem-address indexing (round-to-nearest, no F2I).
// ----------------------------------------------------------------------------

#define GLN 64
#define NTAB 2048
#define S_MAX 24.0f
#define INV_DS ((float)NTAB / S_MAX)
#define W 512
#define TPB 32
#define CHUNK 16
#define NSWEEP 8

struct TabParam { float2 e[NTAB]; };   // 16384 bytes, by value

__device__ __forceinline__ void warp_scan_affine(float& A, float& B, int lane) {
    #pragma unroll
    for (int off = 1; off < 32; off <<= 1) {
        float Ag = __shfl_up_sync(0xFFFFFFFFu, A, off);
        float Bg = __shfl_up_sync(0xFFFFFFFFu, B, off);
        if (lane >= off) { B = fmaf(A, Bg, B); A *= Ag; }
    }
}

__global__ void __launch_bounds__(TPB, 1)
run_kernel(TabParam tp, const float* __restrict__ u,
           float* __restrict__ out, int n) {
    __shared__ float2 tab[NTAB];   // 16 KB
    const int lane = threadIdx.x;

    // table: kernel-param (const bank) -> SMEM, vectorized
    {
        const float4* src = (const float4*)tp.e;
        float4* dst = (float4*)tab;
        #pragma unroll
        for (int j = 0; j < NTAB / 2 / TPB; ++j)
            dst[lane + j * TPB] = src[lane + j * TPB];
    }

    // persistent per-thread state: su2 (u^2), cj (0.52*v_{t-1}), k
    float su2[CHUNK], cj[CHUNK], k[CHUNK];

    const int base = n - W + lane * CHUNK;
    #pragma unroll
    for (int j = 0; j < CHUNK; ++j) {
        int gi = base + j;
        float x = (gi >= 0) ? u[gi] : 0.0f;   // zero-pad front (exact)
        cj[j] = x;                             // stash u temporarily
        su2[j] = x * x;
        k[j] = 0.0f;
    }

    // ---- v scan: v_t = 0.8 v_{t-1} + 0.2 u_t, v_0 = 0; cj = 0.52*v_{t-1} ---
    {
        float A = 1.0f, B = 0.0f;
        float Bp[CHUNK];                       // inclusive B prefix (A = 0.8^j)
        #pragma unroll
        for (int j = 0; j < CHUNK; ++j) {
            B = fmaf(0.8f, B, 0.2f * cj[j]);
            Bp[j] = B;
        }
        A = 0.0281474976710656f;               // 0.8^16
        float As = A, Bs = B;
        warp_scan_affine(As, Bs, lane);
        float vstart = __shfl_up_sync(0xFFFFFFFFu, Bs, 1);
        if (lane == 0) vstart = 0.0f;
        float Aj = 1.0f;
        cj[0] = 0.52f * vstart;
        #pragma unroll
        for (int j = 1; j < CHUNK; ++j) {
            Aj *= 0.8f;                        // 0.8^j
            cj[j] = 0.52f * fmaf(Aj, vstart, Bp[j - 1]);
        }
    }

    __syncwarp();   // table visible

    unsigned sbase = (unsigned)__cvta_generic_to_shared(tab);
    const unsigned OFFC = sbase - 0x58000000u;   // sbase - 8*0x4B000000 mod 2^32
    const float MAGIC = 8388608.0f;              // 2^23 (round-to-nearest)
    const float TMAX  = MAGIC + (float)(NTAB - 1);

    float klast = 0.0f;

    #pragma unroll 1
    for (int sw = 0; sw < NSWEEP; ++sw) {
        float knb = __shfl_up_sync(0xFFFFFFFFu, klast, 1);
        if (lane == 0) knb = 0.0f;

        // fused: lookup + affine coeff + local inclusive compose
        float Al[CHUNK], Bl[CHUNK];
        float A = 1.0f, B = 0.0f;
        #pragma unroll
        for (int j = 0; j < CHUNK; ++j) {
            float kp = (j == 0) ? knb : k[j - 1];
            float s  = fmaf(kp, kp, su2[j]);
            float tt = fminf(fmaf(s, INV_DS, MAGIC), TMAX);
            unsigned addr = __float_as_uint(tt) * 8u + OFFC;
            float a_, b_;
            asm("ld.shared.v2.f32 {%0,%1},[%2];"
                : "=f"(a_), "=f"(b_) : "r"(addr));
            float g  = fmaf(b_, s, a_);
            float at = fmaf(0.28f, g, 0.8f);
            float bt = g * cj[j];
            B = fmaf(at, B, bt);
            A = at * A;
            Al[j] = A; Bl[j] = B;
        }

        // warp scan + exclusive start (k_0 = 0 -> kstart = B_excl)
        float As = A, Bs = B;
        warp_scan_affine(As, Bs, lane);
        float kstart = __shfl_up_sync(0xFFFFFFFFu, Bs, 1);
        if (lane == 0) kstart = 0.0f;

        // rebuild trajectory (independent FMAs)
        #pragma unroll
        for (int j = 0; j < CHUNK; ++j)
            k[j] = fmaf(Al[j], kstart, Bl[j]);
        klast = k[CHUNK - 1];
    }

    if (lane == TPB - 1) *out = tanhf(k[CHUNK - 1]);
}

// ---------------------------------------------------------------------------
// Host: Gauss-Legendre n=64 + table build (double precision, input-indep).
// ---------------------------------------------------------------------------
static void host_leggauss64(double* x, double* w) {
    const int n = GLN;
    const double PI = 3.14159265358979323846;
    for (int i = 0; i < n; ++i) {
        double xi = cos(PI * (i + 0.75) / (n + 0.5));
        double p0 = 1.0, p1 = 0.0, pp = 1.0;
        for (int it = 0; it < 100; ++it) {
            p0 = 1.0; p1 = 0.0;
            for (int j = 1; j <= n; ++j) {
                double p2 = p1; p1 = p0;
                p0 = ((2.0 * j - 1.0) * xi * p1 - (j - 1.0) * p2) / j;
            }
            pp = n * (xi * p0 - p1) / (xi * xi - 1.0);
            double dx = p0 / pp;
            xi -= dx;
            if (fabs(dx) < 1e-15) break;
        }
        p0 = 1.0; p1 = 0.0;
        for (int j = 1; j <= n; ++j) {
            double p2 = p1; p1 = p0;
            p0 = ((2.0 * j - 1.0) * xi * p1 - (j - 1.0) * p2) / j;
        }
        pp = n * (xi * p0 - p1) / (xi * xi - 1.0);
        x[i] = xi;
        w[i] = 2.0 / ((1.0 - xi * xi) * pp * pp);
    }
}

static double host_g(double s, const double* X, const double* EW) {
    double d = sqrt(s);
    double acc = 0.0;
    for (int q = 0; q < GLN; ++q) {
        double th = tanh(d * X[q]);
        acc += EW[q] * (1.0 - th * th);
    }
    return acc * 0.15915494309189535;   // 1/(2*pi)
}

static void host_build_table(TabParam* tp) {
    double x[GLN], wq[GLN], X[GLN], EW[GLN];
    host_leggauss64(x, wq);
    for (int q = 0; q < GLN; ++q) {
        X[q]  = x[q] * 5.0;
        EW[q] = wq[q] * 5.0 * exp(-X[q] * X[q] * 0.5);
    }
    const double ds = (double)S_MAX / (double)NTAB;
    for (int i = 0; i < NTAB; ++i) {
        double s  = i * ds;
        double h  = 0.5 * ds;
        double sl = (s - h > 0.0) ? (s - h) : 0.0;
        double sh = s + h;
        double g0 = host_g(s,  X, EW);
        double gm = host_g(sl, X, EW);
        double gp = host_g(sh, X, EW);
        double bb = (gp - gm) / (sh - sl);
        tp->e[i].x = (float)(g0 - bb * s);
        tp->e[i].y = (float)bb;
    }
}

// ---------------------------------------------------------------------------
extern "C" void kernel_launch(void* const* d_in, const int* in_sizes, int n_in,
                              void* d_out, int out_size) {
    (void)n_in; (void)out_size;
    const float* u = (const float*)d_in[0];
    float* out = (float*)d_out;
    int n = in_sizes[0];

    static TabParam tp;
    host_build_table(&tp);   // deterministic, host-side, input-independent

    run_kernel<<<1, TPB>>>(tp, u, out, n);
}